// round 16
// baseline (speedup 1.0000x reference)
#include <cuda_runtime.h>
#include <cuda_fp16.h>
#include <mma.h>
#include <cstdint>
#include <cstring>

using namespace nvcuda;

#define B_SZ   128
#define T_SZ   256
#define DIN    1024
#define UNITS  1024
#define NG     4096
#define NCLASS 1024

// ---------------- scratch ----------------
__device__ float  g_XP[(size_t)B_SZ * T_SZ * NG];
__device__ __half g_xh[(size_t)B_SZ * T_SZ * DIN];
__device__ __half g_wkh[(size_t)DIN * NG];
__device__ __half g_hT0[UNITS * B_SZ];
__device__ __half g_hT1[UNITS * B_SZ];
__device__ float  g_hrow[B_SZ * UNITS];
__device__ float  g_cbuf[B_SZ * UNITS];
__device__ unsigned g_cnt[8 * 32];        // 8 group arrival counters, 128 B apart, monotonic

__device__ __forceinline__ float sigmf(float x) { return 1.f / (1.f + __expf(-x)); }

__device__ __forceinline__ uint32_t smem_u32(const void* p) {
    return (uint32_t)__cvta_generic_to_shared(p);
}
#define CP16(dst, src) asm volatile("cp.async.cg.shared.global [%0], [%1], 16;\n" :: "r"(dst), "l"(src))
#define CPC()  asm volatile("cp.async.commit_group;\n")
#define CPW1() asm volatile("cp.async.wait_group 1;\n")
#define CPW0() asm volatile("cp.async.wait_group 0;\n")

extern __shared__ float smem[];

// =====================================================================
// float -> half conversion
// =====================================================================
__global__ void f2h_kernel(const float* __restrict__ src, __half* __restrict__ dst, int n4)
{
    int i = blockIdx.x * blockDim.x + threadIdx.x;
    if (i < n4) {
        float4 v = *(const float4*)(src + (size_t)i * 4);
        __half2 a = __floats2half2_rn(v.x, v.y);
        __half2 b = __floats2half2_rn(v.z, v.w);
        uint2 pk;
        memcpy(&pk.x, &a, 4); memcpy(&pk.y, &b, 4);
        *(uint2*)(dst + (size_t)i * 4) = pk;
    }
}

__global__ void h0_to_hT_kernel(const float* __restrict__ h0, __half* __restrict__ hT)
{
    int u = blockIdx.x;
    int b = threadIdx.x;
    hT[u * B_SZ + b] = __float2half(h0[(size_t)b * UNITS + u]);
}

// =====================================================================
// XP = X @ Wk : fp16 WMMA m16n16k16, CTA tile 128x256, warp tile 64x64,
// 3-stage cp.async, fp32 out. 256 threads, 8 warps = 2(M) x 4(N).
// A tile: 128x64 halfs = 1024 x 16B ; B tile: 64x256 halfs = 2048 x 16B.
// =====================================================================
#define XALD 72     // 64 + 8 halfs
#define XBLD 264    // 256 + 8 halfs
#define X_ABUF (128 * XALD)
#define X_BBUF (64 * XBLD)
#define XP_SMEM_BYTES (3 * (X_ABUF + X_BBUF) * 2)   // 156672

__global__ __launch_bounds__(256) void xp_gemm_kernel(const __half* __restrict__ A,
                                                      const __half* __restrict__ Bm,
                                                      float* __restrict__ C)
{
    __half* As = (__half*)smem;
    __half* Bs = As + 3 * X_ABUF;

    const int bm = blockIdx.y, bn = blockIdx.x;
    const int tid = threadIdx.x, wid = tid >> 5;
    const int wm = wid & 1;      // 2 warps over M: 64 rows each
    const int wn = wid >> 1;     // 4 warps over N: 64 cols each
    const __half* aBase = A + (size_t)(bm * 128) * DIN;
    const __half* bBase = Bm + bn * 256;

    wmma::fragment<wmma::accumulator, 16, 16, 16, float> acc[4][4];
#pragma unroll
    for (int i = 0; i < 4; i++)
#pragma unroll
        for (int j = 0; j < 4; j++) wmma::fill_fragment(acc[i][j], 0.0f);

    auto load_chunk = [&](int k, int s) {
        __half* ad = As + s * X_ABUF;
        const __half* asrc = aBase + k * 64;
#pragma unroll
        for (int i = 0; i < 4; i++) {
            int idx = tid + i * 256;          // 1024 x 16B : rows 0..127, 8 chunks each
            int r = idx >> 3, c8 = idx & 7;
            CP16(smem_u32(ad + r * XALD + c8 * 8), asrc + (size_t)r * DIN + c8 * 8);
        }
        __half* bd = Bs + s * X_BBUF;
        const __half* bsrc = bBase + (size_t)(k * 64) * NG;
#pragma unroll
        for (int i = 0; i < 8; i++) {
            int idx = tid + i * 256;          // 2048 x 16B : rows 0..63, 32 chunks each
            int r = idx >> 5, c8 = idx & 31;
            CP16(smem_u32(bd + r * XBLD + c8 * 8), bsrc + (size_t)r * NG + c8 * 8);
        }
        CPC();
    };

    load_chunk(0, 0);
    load_chunk(1, 1);

    for (int k = 0; k < 16; k++) {
        if (k < 15) { CPW1(); } else { CPW0(); }
        __syncthreads();
        if (k + 2 < 16) load_chunk(k + 2, (k + 2) % 3);

        const __half* ab = As + (k % 3) * X_ABUF;
        const __half* bb = Bs + (k % 3) * X_BBUF;
#pragma unroll
        for (int kk = 0; kk < 64; kk += 16) {
            wmma::fragment<wmma::matrix_a, 16, 16, 16, __half, wmma::row_major> af[4];
            wmma::fragment<wmma::matrix_b, 16, 16, 16, __half, wmma::row_major> bf[4];
#pragma unroll
            for (int i = 0; i < 4; i++)
                wmma::load_matrix_sync(af[i], ab + (wm * 64 + i * 16) * XALD + kk, XALD);
#pragma unroll
            for (int j = 0; j < 4; j++)
                wmma::load_matrix_sync(bf[j], bb + kk * XBLD + wn * 64 + j * 16, XBLD);
#pragma unroll
            for (int i = 0; i < 4; i++)
#pragma unroll
                for (int j = 0; j < 4; j++)
                    wmma::mma_sync(acc[i][j], af[i], bf[j], acc[i][j]);
        }
        __syncthreads();
    }

#pragma unroll
    for (int i = 0; i < 4; i++)
#pragma unroll
        for (int j = 0; j < 4; j++) {
            size_t row = (size_t)(bm * 128 + wm * 64 + i * 16);
            size_t col = (size_t)(bn * 256 + wn * 64 + j * 16);
            wmma::store_matrix_sync(&C[row * NG + col], acc[i][j], NG, wmma::mem_row_major);
        }
}

// =====================================================================
// Persistent recurrence: 128 CTAs x 512 threads (16 warps), KC=64,
// grouped-arrival barrier with direct polling. (R14, frozen)
// =====================================================================
#define NTH  512
#define WSLD 40
#define HLD  136
#define KC   64
#define NCH  (UNITS / KC)                // 16

#define WS_HALFS (UNITS * WSLD)
#define HS_STG   (KC * HLD)
#define HS_HALFS (3 * HS_STG)
#define XS_FLTS  (B_SZ * 36)
#define P_FLTS   (5 * 32)

#define OFF_HS_H WS_HALFS
#define OFF_XS_F ((OFF_HS_H + HS_HALFS) / 2)
#define OFF_P_F  (OFF_XS_F + XS_FLTS)
#define PERS_SMEM_BYTES ((OFF_P_F + P_FLTS) * 4)       // 153216

__global__ __launch_bounds__(NTH, 1) void persistent_lstm_kernel(
    const float* __restrict__ Wr,
    const float* __restrict__ br,
    const float* __restrict__ bk,
    const float* __restrict__ alpha,
    const float* __restrict__ beta1,
    const float* __restrict__ beta2,
    const float* __restrict__ c0)
{
    __half* Ws = (__half*)smem;
    __half* Hs = Ws + OFF_HS_H;
    float* Xs  = smem + OFF_XS_F;
    float* Pbk = smem + OFF_P_F;
    float* Pbr = Pbk + 32;
    float* Pal = Pbr + 32;
    float* Pb1 = Pal + 32;
    float* Pb2 = Pb1 + 32;

    const int tid = threadIdx.x;
    const int wid = tid >> 5;
    const int wm = wid & 7;
    const int wn = wid >> 3;
    const int u0 = blockIdx.x * 8;

    for (int it = 0; it < 64; it++) {
        int idx = tid + it * NTH;
        int n = idx & 31, k = idx >> 5;
        Ws[k * WSLD + n] = __float2half(Wr[(size_t)k * NG + (n >> 3) * UNITS + u0 + (n & 7)]);
    }
    if (tid < 32) {
        int jj = (tid >> 3) * UNITS + u0 + (tid & 7);
        Pbk[tid] = bk[jj]; Pbr[tid] = br[jj];
        Pal[tid] = alpha[jj]; Pb1[tid] = beta1[jj]; Pb2[tid] = beta2[jj];
    }
    const int cu = tid >> 6;
    const int cb0 = (tid & 63) * 2;
    float creg[2];
#pragma unroll
    for (int i = 0; i < 2; i++)
        creg[i] = c0[(size_t)(cb0 + i) * UNITS + u0 + cu];
    __syncthreads();

    for (int t = 0; t < T_SZ; t++) {
        const __half* hT = (t & 1) ? g_hT1 : g_hT0;
        __half* hTn = (t & 1) ? g_hT0 : g_hT1;

        wmma::fragment<wmma::accumulator, 16, 16, 16, float> acc;
        wmma::fill_fragment(acc, 0.0f);

        auto load_chunk = [&](int kc, int s) {
            __half* hd = Hs + s * HS_STG;
            const __half* hsrc = hT + kc * KC * B_SZ;
#pragma unroll
            for (int j = 0; j < 2; j++) {
                int i = tid + j * NTH;
                int kr = i >> 4, b8 = (i & 15) * 8;
                CP16(smem_u32(hd + kr * HLD + b8), hsrc + kr * B_SZ + b8);
            }
            if (kc == 0) {
#pragma unroll
                for (int j = 0; j < 2; j++) {
                    int i = tid + j * NTH;
                    int b = i >> 3, q = i & 7;
                    int g = q >> 1, part = q & 1;
                    CP16(smem_u32(Xs + b * 36 + g * 8 + part * 4),
                         g_XP + ((size_t)b * T_SZ + t) * NG + g * UNITS + u0 + part * 4);
                }
            }
            CPC();
        };

        load_chunk(0, 0);
        load_chunk(1, 1);

        for (int kc = 0; kc < NCH; kc++) {
            if (kc < NCH - 1) { CPW1(); } else { CPW0(); }
            __syncthreads();
            if (kc + 2 < NCH) load_chunk(kc + 2, (kc + 2) % 3);

            const __half* hb = Hs + (kc % 3) * HS_STG;
            const __half* wb = Ws + kc * KC * WSLD;
#pragma unroll
            for (int kk = 0; kk < KC; kk += 16) {
                wmma::fragment<wmma::matrix_a, 16, 16, 16, __half, wmma::col_major> af;
                wmma::fragment<wmma::matrix_b, 16, 16, 16, __half, wmma::row_major> bf;
                wmma::load_matrix_sync(af, hb + kk * HLD + wm * 16, HLD);
                wmma::load_matrix_sync(bf, wb + kk * WSLD + wn * 16, WSLD);
                wmma::mma_sync(acc, af, bf, acc);
            }
        }
        __syncthreads();

        float* Zs = (float*)Hs;
        wmma::store_matrix_sync(Zs + (wm * 16) * 36 + wn * 16, acc, 36, wmma::mem_row_major);
        __syncthreads();

        float hout[2];
#pragma unroll
        for (int i = 0; i < 2; i++) {
            int b = cb0 + i;
            float z[4];
#pragma unroll
            for (int g = 0; g < 4; g++) {
                int cc = g * 8 + cu;
                float hp = Zs[b * 36 + cc] + Pbr[cc];
                float xv = Xs[b * 36 + cc] + Pbk[cc];
                z[g] = Pal[cc] * xv * hp + Pb1[cc] * xv + Pb2[cc] * hp;
            }
            float cn = tanhf(z[2]) * sigmf(z[0]) + creg[i] * sigmf(z[1]);
            float hn = tanhf(cn) * sigmf(z[3]);
            creg[i] = cn;
            hout[i] = hn;
        }
        __half2 p0 = __floats2half2_rn(hout[0], hout[1]);
        unsigned pk;
        memcpy(&pk, &p0, 4);
        *(unsigned*)(hTn + (u0 + cu) * B_SZ + cb0) = pk;

        if (t == T_SZ - 1) {
#pragma unroll
            for (int i = 0; i < 2; i++) {
                g_hrow[(size_t)(cb0 + i) * UNITS + u0 + cu] = hout[i];
                g_cbuf[(size_t)(cb0 + i) * UNITS + u0 + cu] = creg[i];
            }
        }

        __threadfence();
        __syncthreads();
        if (tid == 0) {
            const unsigned target = 16u * (unsigned)(t + 1);
            atomicAdd(&g_cnt[(blockIdx.x & 7) * 32], 1u);
            volatile unsigned* cnt = (volatile unsigned*)g_cnt;
            for (;;) {
                bool done = true;
#pragma unroll
                for (int g = 0; g < 8; g++)
                    done &= (cnt[g * 32] >= target);
                if (done) break;
                __nanosleep(32);
            }
            __threadfence();
        }
        __syncthreads();
    }
}

// =====================================================================
// classifier: out = h @ Wc + bc, tiled fp32 (64x64 tiles)
// =====================================================================
__global__ __launch_bounds__(256) void classify_kernel(const float* __restrict__ h,
                                                       const float* __restrict__ Wc,
                                                       const float* __restrict__ bc,
                                                       float* __restrict__ out)
{
    __shared__ float Hsm[64][17];
    __shared__ float Wsm[16][65];

    const int tid = threadIdx.x;
    const int tx = tid & 15, ty = tid >> 4;
    const int col0 = blockIdx.x * 64;
    const int row0 = blockIdx.y * 64;

    float acc[4][4] = {};

    for (int k0 = 0; k0 < UNITS; k0 += 16) {
        {
            int r = tid >> 2, kof = (tid & 3) * 4;
            float4 v = *(const float4*)&h[(size_t)(row0 + r) * UNITS + k0 + kof];
            Hsm[r][kof] = v.x; Hsm[r][kof + 1] = v.y; Hsm[r][kof + 2] = v.z; Hsm[r][kof + 3] = v.w;
        }
        {
            int kk = tid >> 4, c4 = (tid & 15) * 4;
            float4 v = *(const float4*)&Wc[(size_t)(k0 + kk) * NCLASS + col0 + c4];
            Wsm[kk][c4] = v.x; Wsm[kk][c4 + 1] = v.y; Wsm[kk][c4 + 2] = v.z; Wsm[kk][c4 + 3] = v.w;
        }
        __syncthreads();
#pragma unroll
        for (int kk = 0; kk < 16; kk++) {
            float a[4], b[4];
#pragma unroll
            for (int i = 0; i < 4; i++) a[i] = Hsm[ty * 4 + i][kk];
#pragma unroll
            for (int j = 0; j < 4; j++) b[j] = Wsm[kk][tx * 4 + j];
#pragma unroll
            for (int i = 0; i < 4; i++)
#pragma unroll
                for (int j = 0; j < 4; j++)
                    acc[i][j] += a[i] * b[j];
        }
        __syncthreads();
    }

#pragma unroll
    for (int i = 0; i < 4; i++)
#pragma unroll
        for (int j = 0; j < 4; j++)
            out[(size_t)(row0 + ty * 4 + i) * NCLASS + col0 + tx * 4 + j] =
                acc[i][j] + bc[col0 + tx * 4 + j];
}

// =====================================================================
// launch
// =====================================================================
extern "C" void kernel_launch(void* const* d_in, const int* in_sizes, int n_in,
                              void* d_out, int out_size)
{
    const float* x     = (const float*)d_in[0];
    const float* h0    = (const float*)d_in[1];
    const float* c0    = (const float*)d_in[2];
    const float* Wk    = (const float*)d_in[3];
    const float* bk    = (const float*)d_in[4];
    const float* Wr    = (const float*)d_in[5];
    const float* br    = (const float*)d_in[6];
    const float* alpha = (const float*)d_in[7];
    const float* beta1 = (const float*)d_in[8];
    const float* beta2 = (const float*)d_in[9];
    const float* Wc    = (const float*)d_in[10];
    const float* bc    = (const float*)d_in[11];
    float* out = (float*)d_out;

    float *pXP, *pHrow, *pC;
    __half *pXH, *pWKH, *pHT0;
    cudaGetSymbolAddress((void**)&pXP, g_XP);
    cudaGetSymbolAddress((void**)&pXH, g_xh);
    cudaGetSymbolAddress((void**)&pWKH, g_wkh);
    cudaGetSymbolAddress((void**)&pHT0, g_hT0);
    cudaGetSymbolAddress((void**)&pHrow, g_hrow);
    cudaGetSymbolAddress((void**)&pC, g_cbuf);
    void *pCnt;
    cudaGetSymbolAddress(&pCnt, g_cnt);

    cudaFuncSetAttribute(xp_gemm_kernel, cudaFuncAttributeMaxDynamicSharedMemorySize, XP_SMEM_BYTES);
    cudaFuncSetAttribute(persistent_lstm_kernel, cudaFuncAttributeMaxDynamicSharedMemorySize, PERS_SMEM_BYTES);

    cudaMemsetAsync(pCnt, 0, 8 * 32 * sizeof(unsigned));

    f2h_kernel<<<(B_SZ * T_SZ * DIN / 4 + 255) / 256, 256>>>(x, pXH, B_SZ * T_SZ * DIN / 4);
    f2h_kernel<<<(DIN * NG / 4 + 255) / 256, 256>>>(Wk, pWKH, DIN * NG / 4);
    h0_to_hT_kernel<<<UNITS, B_SZ>>>(h0, pHT0);

    xp_gemm_kernel<<<dim3(NG / 256, (B_SZ * T_SZ) / 128), 256, XP_SMEM_BYTES>>>(pXH, pWKH, pXP);

    persistent_lstm_kernel<<<UNITS / 8, NTH, PERS_SMEM_BYTES>>>(
        Wr, br, bk, alpha, beta1, beta2, c0);

    classify_kernel<<<dim3(NCLASS / 64, B_SZ / 64), 256>>>(pHrow, Wc, bc, out);

    const size_t stateBytes = (size_t)B_SZ * UNITS * sizeof(float);
    cudaMemcpyAsync(out + (size_t)B_SZ * NCLASS, pHrow, stateBytes, cudaMemcpyDeviceToDevice);
    cudaMemcpyAsync(out + (size_t)B_SZ * NCLASS + (size_t)B_SZ * UNITS, pC, stateBytes,
                    cudaMemcpyDeviceToDevice);
}

// round 17
// speedup vs baseline: 1.0430x; 1.0430x over previous
#include <cuda_runtime.h>
#include <cuda_fp16.h>
#include <mma.h>
#include <cstdint>
#include <cstring>

using namespace nvcuda;

#define B_SZ   128
#define T_SZ   256
#define DIN    1024
#define UNITS  1024
#define NG     4096
#define NCLASS 1024

// ---------------- scratch ----------------
__device__ float  g_XP[(size_t)B_SZ * T_SZ * NG];
__device__ __half g_xh[(size_t)B_SZ * T_SZ * DIN];
__device__ __half g_wkh[(size_t)DIN * NG];
__device__ __half g_hT0[UNITS * B_SZ];
__device__ __half g_hT1[UNITS * B_SZ];
__device__ float  g_hrow[B_SZ * UNITS];
__device__ float  g_cbuf[B_SZ * UNITS];
__device__ unsigned g_cnt[8 * 32];        // 8 group arrival counters, 128 B apart, monotonic

__device__ __forceinline__ float sigmf(float x) { return 1.f / (1.f + __expf(-x)); }

__device__ __forceinline__ uint32_t smem_u32(const void* p) {
    return (uint32_t)__cvta_generic_to_shared(p);
}
#define CP16(dst, src) asm volatile("cp.async.cg.shared.global [%0], [%1], 16;\n" :: "r"(dst), "l"(src))
#define CPC()  asm volatile("cp.async.commit_group;\n")
#define CPW1() asm volatile("cp.async.wait_group 1;\n")
#define CPW0() asm volatile("cp.async.wait_group 0;\n")

extern __shared__ float smem[];

// =====================================================================
// float -> half conversion
// =====================================================================
__global__ void f2h_kernel(const float* __restrict__ src, __half* __restrict__ dst, int n4)
{
    int i = blockIdx.x * blockDim.x + threadIdx.x;
    if (i < n4) {
        float4 v = *(const float4*)(src + (size_t)i * 4);
        __half2 a = __floats2half2_rn(v.x, v.y);
        __half2 b = __floats2half2_rn(v.z, v.w);
        uint2 pk;
        memcpy(&pk.x, &a, 4); memcpy(&pk.y, &b, 4);
        *(uint2*)(dst + (size_t)i * 4) = pk;
    }
}

__global__ void h0_to_hT_kernel(const float* __restrict__ h0, __half* __restrict__ hT)
{
    int u = blockIdx.x;
    int b = threadIdx.x;
    hT[u * B_SZ + b] = __float2half(h0[(size_t)b * UNITS + u]);
}

// =====================================================================
// XP = X @ Wk : fp16 WMMA m16n16k16, CTA 128x128, warp 32x64,
// 3-stage cp.async, fp32 out. (R14 proven: 737 us, 126 regs, 2 CTAs/SM)
// =====================================================================
#define XALD 72
#define XBLD 136
#define X_ABUF (128 * XALD)
#define X_BBUF (64 * XBLD)
#define XP_SMEM_BYTES (3 * (X_ABUF + X_BBUF) * 2)

__global__ __launch_bounds__(256) void xp_gemm_kernel(const __half* __restrict__ A,
                                                      const __half* __restrict__ Bm,
                                                      float* __restrict__ C)
{
    __half* As = (__half*)smem;
    __half* Bs = As + 3 * X_ABUF;

    const int bm = blockIdx.y, bn = blockIdx.x;
    const int tid = threadIdx.x, wid = tid >> 5;
    const int wm = wid & 3, wn = wid >> 2;
    const __half* aBase = A + (size_t)(bm * 128) * DIN;
    const __half* bBase = Bm + bn * 128;

    wmma::fragment<wmma::accumulator, 16, 16, 16, float> acc[2][4];
#pragma unroll
    for (int i = 0; i < 2; i++)
#pragma unroll
        for (int j = 0; j < 4; j++) wmma::fill_fragment(acc[i][j], 0.0f);

    auto load_chunk = [&](int k, int s) {
        __half* ad = As + s * X_ABUF;
        const __half* asrc = aBase + k * 64;
#pragma unroll
        for (int i = 0; i < 4; i++) {
            int idx = tid + i * 256;
            int r = idx >> 3, c8 = idx & 7;
            CP16(smem_u32(ad + r * XALD + c8 * 8), asrc + (size_t)r * DIN + c8 * 8);
        }
        __half* bd = Bs + s * X_BBUF;
        const __half* bsrc = bBase + (size_t)(k * 64) * NG;
#pragma unroll
        for (int i = 0; i < 4; i++) {
            int idx = tid + i * 256;
            int r = idx >> 4, c8 = idx & 15;
            CP16(smem_u32(bd + r * XBLD + c8 * 8), bsrc + (size_t)r * NG + c8 * 8);
        }
        CPC();
    };

    load_chunk(0, 0);
    load_chunk(1, 1);

    for (int k = 0; k < 16; k++) {
        if (k < 15) { CPW1(); } else { CPW0(); }
        __syncthreads();
        if (k + 2 < 16) load_chunk(k + 2, (k + 2) % 3);

        const __half* ab = As + (k % 3) * X_ABUF;
        const __half* bb = Bs + (k % 3) * X_BBUF;
#pragma unroll
        for (int kk = 0; kk < 64; kk += 16) {
            wmma::fragment<wmma::matrix_a, 16, 16, 16, __half, wmma::row_major> af[2];
            wmma::fragment<wmma::matrix_b, 16, 16, 16, __half, wmma::row_major> bf[4];
#pragma unroll
            for (int i = 0; i < 2; i++)
                wmma::load_matrix_sync(af[i], ab + (wm * 32 + i * 16) * XALD + kk, XALD);
#pragma unroll
            for (int j = 0; j < 4; j++)
                wmma::load_matrix_sync(bf[j], bb + kk * XBLD + wn * 64 + j * 16, XBLD);
#pragma unroll
            for (int i = 0; i < 2; i++)
#pragma unroll
                for (int j = 0; j < 4; j++)
                    wmma::mma_sync(acc[i][j], af[i], bf[j], acc[i][j]);
        }
        __syncthreads();
    }

#pragma unroll
    for (int i = 0; i < 2; i++)
#pragma unroll
        for (int j = 0; j < 4; j++) {
            size_t row = (size_t)(bm * 128 + wm * 32 + i * 16);
            size_t col = (size_t)(bn * 128 + wn * 64 + j * 16);
            wmma::store_matrix_sync(&C[row * NG + col], acc[i][j], NG, wmma::mem_row_major);
        }
}

// =====================================================================
// Persistent recurrence: 128 CTAs x 512 threads (16 warps), KC=64,
// grouped-arrival barrier, SINGLE-THREAD cumulative fence.
// CTA: units [u0,u0+8) => 32 gate-cols, M=128, K=1024.
// =====================================================================
#define NTH  512
#define WSLD 40
#define HLD  136
#define KC   64
#define NCH  (UNITS / KC)                // 16

#define WS_HALFS (UNITS * WSLD)
#define HS_STG   (KC * HLD)
#define HS_HALFS (3 * HS_STG)
#define XS_FLTS  (B_SZ * 36)
#define P_FLTS   (5 * 32)

#define OFF_HS_H WS_HALFS
#define OFF_XS_F ((OFF_HS_H + HS_HALFS) / 2)
#define OFF_P_F  (OFF_XS_F + XS_FLTS)
#define PERS_SMEM_BYTES ((OFF_P_F + P_FLTS) * 4)       // 153216

__global__ __launch_bounds__(NTH, 1) void persistent_lstm_kernel(
    const float* __restrict__ Wr,
    const float* __restrict__ br,
    const float* __restrict__ bk,
    const float* __restrict__ alpha,
    const float* __restrict__ beta1,
    const float* __restrict__ beta2,
    const float* __restrict__ c0)
{
    __half* Ws = (__half*)smem;
    __half* Hs = Ws + OFF_HS_H;
    float* Xs  = smem + OFF_XS_F;
    float* Pbk = smem + OFF_P_F;
    float* Pbr = Pbk + 32;
    float* Pal = Pbr + 32;
    float* Pb1 = Pal + 32;
    float* Pb2 = Pb1 + 32;

    const int tid = threadIdx.x;
    const int wid = tid >> 5;
    const int wm = wid & 7;      // 8 warps over M: 16 rows each
    const int wn = wid >> 3;     // 2 warps over N: 16 cols each
    const int u0 = blockIdx.x * 8;

    for (int it = 0; it < 64; it++) {
        int idx = tid + it * NTH;
        int n = idx & 31, k = idx >> 5;
        Ws[k * WSLD + n] = __float2half(Wr[(size_t)k * NG + (n >> 3) * UNITS + u0 + (n & 7)]);
    }
    if (tid < 32) {
        int jj = (tid >> 3) * UNITS + u0 + (tid & 7);
        Pbk[tid] = bk[jj]; Pbr[tid] = br[jj];
        Pal[tid] = alpha[jj]; Pb1[tid] = beta1[jj]; Pb2[tid] = beta2[jj];
    }
    const int cu = tid >> 6;           // unit 0..7
    const int cb0 = (tid & 63) * 2;    // batch rows cb0, cb0+1
    float creg[2];
#pragma unroll
    for (int i = 0; i < 2; i++)
        creg[i] = c0[(size_t)(cb0 + i) * UNITS + u0 + cu];
    __syncthreads();

    for (int t = 0; t < T_SZ; t++) {
        const __half* hT = (t & 1) ? g_hT1 : g_hT0;
        __half* hTn = (t & 1) ? g_hT0 : g_hT1;

        wmma::fragment<wmma::accumulator, 16, 16, 16, float> acc;
        wmma::fill_fragment(acc, 0.0f);

        auto load_chunk = [&](int kc, int s) {
            __half* hd = Hs + s * HS_STG;
            const __half* hsrc = hT + kc * KC * B_SZ;
#pragma unroll
            for (int j = 0; j < 2; j++) {
                int i = tid + j * NTH;        // 1024 x 16B
                int kr = i >> 4, b8 = (i & 15) * 8;
                CP16(smem_u32(hd + kr * HLD + b8), hsrc + kr * B_SZ + b8);
            }
            if (kc == 0) {
#pragma unroll
                for (int j = 0; j < 2; j++) {
                    int i = tid + j * NTH;    // 1024 x 16B
                    int b = i >> 3, q = i & 7;
                    int g = q >> 1, part = q & 1;
                    CP16(smem_u32(Xs + b * 36 + g * 8 + part * 4),
                         g_XP + ((size_t)b * T_SZ + t) * NG + g * UNITS + u0 + part * 4);
                }
            }
            CPC();
        };

        load_chunk(0, 0);
        load_chunk(1, 1);

        for (int kc = 0; kc < NCH; kc++) {
            if (kc < NCH - 1) { CPW1(); } else { CPW0(); }
            __syncthreads();
            if (kc + 2 < NCH) load_chunk(kc + 2, (kc + 2) % 3);

            const __half* hb = Hs + (kc % 3) * HS_STG;
            const __half* wb = Ws + kc * KC * WSLD;
#pragma unroll
            for (int kk = 0; kk < KC; kk += 16) {
                wmma::fragment<wmma::matrix_a, 16, 16, 16, __half, wmma::col_major> af;
                wmma::fragment<wmma::matrix_b, 16, 16, 16, __half, wmma::row_major> bf;
                wmma::load_matrix_sync(af, hb + kk * HLD + wm * 16, HLD);
                wmma::load_matrix_sync(bf, wb + kk * WSLD + wn * 16, WSLD);
                wmma::mma_sync(acc, af, bf, acc);
            }
        }
        __syncthreads();   // Hs free

        float* Zs = (float*)Hs;
        wmma::store_matrix_sync(Zs + (wm * 16) * 36 + wn * 16, acc, 36, wmma::mem_row_major);
        __syncthreads();

        float hout[2];
#pragma unroll
        for (int i = 0; i < 2; i++) {
            int b = cb0 + i;
            float z[4];
#pragma unroll
            for (int g = 0; g < 4; g++) {
                int cc = g * 8 + cu;
                float hp = Zs[b * 36 + cc] + Pbr[cc];
                float xv = Xs[b * 36 + cc] + Pbk[cc];
                z[g] = Pal[cc] * xv * hp + Pb1[cc] * xv + Pb2[cc] * hp;
            }
            float cn = tanhf(z[2]) * sigmf(z[0]) + creg[i] * sigmf(z[1]);
            float hn = tanhf(cn) * sigmf(z[3]);
            creg[i] = cn;
            hout[i] = hn;
        }
        __half2 p0 = __floats2half2_rn(hout[0], hout[1]);
        unsigned pk;
        memcpy(&pk, &p0, 4);
        *(unsigned*)(hTn + (u0 + cu) * B_SZ + cb0) = pk;

        if (t == T_SZ - 1) {
#pragma unroll
            for (int i = 0; i < 2; i++) {
                g_hrow[(size_t)(cb0 + i) * UNITS + u0 + cu] = hout[i];
                g_cbuf[(size_t)(cb0 + i) * UNITS + u0 + cu] = creg[i];
            }
        }

        // ---- barrier: syncthreads releases all stores to tid0; tid0's
        //      GPU fence is cumulative -> one MEMBAR instead of 512 ----
        __syncthreads();
        if (tid == 0) {
            __threadfence();
            const unsigned target = 16u * (unsigned)(t + 1);
            atomicAdd(&g_cnt[(blockIdx.x & 7) * 32], 1u);
            volatile unsigned* cnt = (volatile unsigned*)g_cnt;
            for (;;) {
                bool done = true;
#pragma unroll
                for (int g = 0; g < 8; g++)
                    done &= (cnt[g * 32] >= target);
                if (done) break;
                __nanosleep(32);
            }
            __threadfence();
        }
        __syncthreads();
    }
}

// =====================================================================
// classifier: out = h @ Wc + bc (fp32 naive, proven 72 us)
// =====================================================================
__global__ void classify_kernel(const float* __restrict__ h,
                                const float* __restrict__ Wc,
                                const float* __restrict__ bc,
                                float* __restrict__ out)
{
    int col = blockIdx.x * 256 + threadIdx.x;
    int b = blockIdx.y;
    const float* hr = &h[(size_t)b * UNITS];
    float s = 0.f;
#pragma unroll 8
    for (int k = 0; k < UNITS; k++)
        s += hr[k] * Wc[(size_t)k * NCLASS + col];
    out[(size_t)b * NCLASS + col] = s + bc[col];
}

// =====================================================================
// launch
// =====================================================================
extern "C" void kernel_launch(void* const* d_in, const int* in_sizes, int n_in,
                              void* d_out, int out_size)
{
    const float* x     = (const float*)d_in[0];
    const float* h0    = (const float*)d_in[1];
    const float* c0    = (const float*)d_in[2];
    const float* Wk    = (const float*)d_in[3];
    const float* bk    = (const float*)d_in[4];
    const float* Wr    = (const float*)d_in[5];
    const float* br    = (const float*)d_in[6];
    const float* alpha = (const float*)d_in[7];
    const float* beta1 = (const float*)d_in[8];
    const float* beta2 = (const float*)d_in[9];
    const float* Wc    = (const float*)d_in[10];
    const float* bc    = (const float*)d_in[11];
    float* out = (float*)d_out;

    float *pXP, *pHrow, *pC;
    __half *pXH, *pWKH, *pHT0;
    cudaGetSymbolAddress((void**)&pXP, g_XP);
    cudaGetSymbolAddress((void**)&pXH, g_xh);
    cudaGetSymbolAddress((void**)&pWKH, g_wkh);
    cudaGetSymbolAddress((void**)&pHT0, g_hT0);
    cudaGetSymbolAddress((void**)&pHrow, g_hrow);
    cudaGetSymbolAddress((void**)&pC, g_cbuf);
    void *pCnt;
    cudaGetSymbolAddress(&pCnt, g_cnt);

    cudaFuncSetAttribute(xp_gemm_kernel, cudaFuncAttributeMaxDynamicSharedMemorySize, XP_SMEM_BYTES);
    cudaFuncSetAttribute(persistent_lstm_kernel, cudaFuncAttributeMaxDynamicSharedMemorySize, PERS_SMEM_BYTES);

    cudaMemsetAsync(pCnt, 0, 8 * 32 * sizeof(unsigned));

    f2h_kernel<<<(B_SZ * T_SZ * DIN / 4 + 255) / 256, 256>>>(x, pXH, B_SZ * T_SZ * DIN / 4);
    f2h_kernel<<<(DIN * NG / 4 + 255) / 256, 256>>>(Wk, pWKH, DIN * NG / 4);
    h0_to_hT_kernel<<<UNITS, B_SZ>>>(h0, pHT0);

    xp_gemm_kernel<<<dim3(NG / 128, (B_SZ * T_SZ) / 128), 256, XP_SMEM_BYTES>>>(pXH, pWKH, pXP);

    persistent_lstm_kernel<<<UNITS / 8, NTH, PERS_SMEM_BYTES>>>(
        Wr, br, bk, alpha, beta1, beta2, c0);

    classify_kernel<<<dim3(NCLASS / 256, B_SZ), 256>>>(pHrow, Wc, bc, out);

    const size_t stateBytes = (size_t)B_SZ * UNITS * sizeof(float);
    cudaMemcpyAsync(out + (size_t)B_SZ * NCLASS, pHrow, stateBytes, cudaMemcpyDeviceToDevice);
    cudaMemcpyAsync(out + (size_t)B_SZ * NCLASS + (size_t)B_SZ * UNITS, pC, stateBytes,
                    cudaMemcpyDeviceToDevice);
}